// round 1
// baseline (speedup 1.0000x reference)
#include <cuda_runtime.h>

#define Bsz 512
#define Tsz 256
#define Fsz 256
#define Hsz 512

// Ping-pong hidden state + cell state scratch (no allocation allowed).
__device__ float d_hbuf[2][Bsz * Hsz];
__device__ float d_c[Bsz * Hsz];

__global__ void init_state_kernel() {
    int i = blockIdx.x * blockDim.x + threadIdx.x;
    if (i < Bsz * Hsz) {
        d_hbuf[0][i] = 0.f;
        d_c[i] = 0.f;
    }
}

// One LSTM time step, fully fused:
//   gates[b, g*512+n] = sum_k h[b,k]*W_hh[g*512+n,k] + sum_f x[b,t,f]*W_ih[g*512+n,f] + b_ih + b_hh
// then pointwise cell update. Grid: (512/64) x (512/32) = 128 blocks, 256 threads.
// Thread micro-tile: 4 batch x 2 hidden x 4 gates = 32 accumulators.
__global__ __launch_bounds__(256, 1)
void lstm_step_kernel(const float* __restrict__ x,
                      const float* __restrict__ Wih,
                      const float* __restrict__ Whh,
                      const float* __restrict__ bih,
                      const float* __restrict__ bhh,
                      int t)
{
    __shared__ __align__(16) float Hs[16][64];      // [k][b]
    __shared__ __align__(16) float Ws[4][16][32];   // [gate][k][n]

    const int tid = threadIdx.x;
    const int tx = tid & 15;   // hidden pairs: n = n0 + tx*2 + {0,1}
    const int ty = tid >> 4;   // batch quads:  b = b0 + ty*4 + {0..3}
    const int b0 = blockIdx.x * 64;
    const int n0 = blockIdx.y * 32;

    const float* __restrict__ hin  = d_hbuf[t & 1];
    float* __restrict__       hout = d_hbuf[(t + 1) & 1];

    float acc[4][4][2];  // [bi][gate][ni]
    #pragma unroll
    for (int bi = 0; bi < 4; bi++)
        #pragma unroll
        for (int g = 0; g < 4; g++) {
            acc[bi][g][0] = 0.f;
            acc[bi][g][1] = 0.f;
        }

    const int lrow = tid >> 2;        // 0..63 (batch row for Hs load)
    const int lk   = (tid & 3) * 4;   // 0,4,8,12

    // K loop over [h (512) | x_t (256)] = 768, BK = 16 -> 48 chunks
    for (int k0 = 0; k0 < Hsz + Fsz; k0 += 16) {
        // ---- global loads into registers ----
        float4 hv;
        if (k0 < Hsz)
            hv = *(const float4*)(hin + (size_t)(b0 + lrow) * Hsz + k0 + lk);
        else
            hv = *(const float4*)(x + ((size_t)(b0 + lrow) * Tsz + t) * Fsz + (k0 - Hsz) + lk);

        float4 wv[2];
        int wg[2], wn[2], wkk[2];
        #pragma unroll
        for (int j = 0; j < 2; j++) {
            int q = tid + j * 256;     // float4 index 0..511
            int r = q >> 2;            // weight row 0..127 within tile
            wg[j]  = r >> 5;           // gate 0..3
            wn[j]  = r & 31;           // hidden col 0..31
            wkk[j] = (q & 3) * 4;      // k sub-offset 0,4,8,12
            int n4 = wg[j] * Hsz + n0 + wn[j];
            if (k0 < Hsz)
                wv[j] = *(const float4*)(Whh + (size_t)n4 * Hsz + k0 + wkk[j]);
            else
                wv[j] = *(const float4*)(Wih + (size_t)n4 * Fsz + (k0 - Hsz) + wkk[j]);
        }

        // ---- stage into shared ----
        Hs[lk + 0][lrow] = hv.x;
        Hs[lk + 1][lrow] = hv.y;
        Hs[lk + 2][lrow] = hv.z;
        Hs[lk + 3][lrow] = hv.w;
        #pragma unroll
        for (int j = 0; j < 2; j++) {
            Ws[wg[j]][wkk[j] + 0][wn[j]] = wv[j].x;
            Ws[wg[j]][wkk[j] + 1][wn[j]] = wv[j].y;
            Ws[wg[j]][wkk[j] + 2][wn[j]] = wv[j].z;
            Ws[wg[j]][wkk[j] + 3][wn[j]] = wv[j].w;
        }
        __syncthreads();

        // ---- FMA core ----
        #pragma unroll
        for (int kk = 0; kk < 16; kk++) {
            float4 a = *(const float4*)&Hs[kk][ty * 4];
            float av[4] = {a.x, a.y, a.z, a.w};
            float2 w0 = *(const float2*)&Ws[0][kk][tx * 2];
            float2 w1 = *(const float2*)&Ws[1][kk][tx * 2];
            float2 w2 = *(const float2*)&Ws[2][kk][tx * 2];
            float2 w3 = *(const float2*)&Ws[3][kk][tx * 2];
            #pragma unroll
            for (int bi = 0; bi < 4; bi++) {
                acc[bi][0][0] += av[bi] * w0.x;  acc[bi][0][1] += av[bi] * w0.y;
                acc[bi][1][0] += av[bi] * w1.x;  acc[bi][1][1] += av[bi] * w1.y;
                acc[bi][2][0] += av[bi] * w2.x;  acc[bi][2][1] += av[bi] * w2.y;
                acc[bi][3][0] += av[bi] * w3.x;  acc[bi][3][1] += av[bi] * w3.y;
            }
        }
        __syncthreads();
    }

    // ---- epilogue: bias + activations + state update ----
    #pragma unroll
    for (int ni = 0; ni < 2; ni++) {
        int n = n0 + tx * 2 + ni;
        float bI = bih[n]        + bhh[n];
        float bF = bih[n +  512] + bhh[n +  512];
        float bG = bih[n + 1024] + bhh[n + 1024];
        float bO = bih[n + 1536] + bhh[n + 1536];
        #pragma unroll
        for (int bi = 0; bi < 4; bi++) {
            int b = b0 + ty * 4 + bi;
            float gi = acc[bi][0][ni] + bI;
            float gf = acc[bi][1][ni] + bF;
            float gg = acc[bi][2][ni] + bG;
            float go = acc[bi][3][ni] + bO;
            float iv = 1.f / (1.f + expf(-gi));
            float fv = 1.f / (1.f + expf(-gf));
            float gv = tanhf(gg);
            float ov = 1.f / (1.f + expf(-go));
            int idx = b * Hsz + n;
            float cn = fv * d_c[idx] + iv * gv;
            d_c[idx] = cn;
            hout[idx] = ov * tanhf(cn);
        }
    }
}

// out[b] = h_final[b,:] . W_out[0,:] + b_out[0]; one warp per batch row.
__global__ void head_kernel(const float* __restrict__ Wout,
                            const float* __restrict__ bout,
                            float* __restrict__ out)
{
    int w    = (blockIdx.x * blockDim.x + threadIdx.x) >> 5;
    int lane = threadIdx.x & 31;
    if (w >= Bsz) return;
    const float* hr = d_hbuf[0] + (size_t)w * Hsz;  // t=255 writes buf 0
    float s = 0.f;
    for (int k = lane; k < Hsz; k += 32) s += hr[k] * Wout[k];
    #pragma unroll
    for (int o = 16; o > 0; o >>= 1) s += __shfl_xor_sync(0xffffffffu, s, o);
    if (lane == 0) out[w] = s + bout[0];
}

extern "C" void kernel_launch(void* const* d_in, const int* in_sizes, int n_in,
                              void* d_out, int out_size)
{
    const float* x    = (const float*)d_in[0];
    const float* Wih  = (const float*)d_in[1];
    const float* Whh  = (const float*)d_in[2];
    const float* bih  = (const float*)d_in[3];
    const float* bhh  = (const float*)d_in[4];
    const float* Wout = (const float*)d_in[5];
    const float* bout = (const float*)d_in[6];
    float* out = (float*)d_out;
    (void)in_sizes; (void)n_in; (void)out_size;

    init_state_kernel<<<(Bsz * Hsz + 255) / 256, 256>>>();

    dim3 grid(Bsz / 64, Hsz / 32);  // 8 x 16 = 128 blocks
    for (int t = 0; t < Tsz; t++)
        lstm_step_kernel<<<grid, 256>>>(x, Wih, Whh, bih, bhh, t);

    head_kernel<<<64, 256>>>(Wout, bout, out);
}